// round 3
// baseline (speedup 1.0000x reference)
#include <cuda_runtime.h>
#include <math_constants.h>

// ChamferDistanceLoss: B=8, N=4096, D=3.
// d(q,c) = |q|^2 + |c|^2 - 2 q.c ; per-query min folded as qn + min_c(cn - 2 dot).
// Packed-pair math: fma.rn.f32x2 (FFMA2) computes 2 queries per instruction.
// Candidates staged in smem pre-duplicated so packed operands load directly.

#define NPTS 4096
#define BATCH 8
#define MAIN_THREADS 128
#define QTILE 256                 // queries per block (2 per thread)
#define CTILE 512                 // candidates staged per smem tile
#define MAIN_BLOCKS 256           // 2 dir * 8 batch * 16 qtiles

__device__ float g_partial[MAIN_BLOCKS];

typedef unsigned long long u64;

__device__ __forceinline__ u64 pack2(float lo, float hi) {
    u64 v; asm("mov.b64 %0, {%1, %2};" : "=l"(v) : "f"(lo), "f"(hi)); return v;
}
__device__ __forceinline__ void unpack2(u64 v, float& lo, float& hi) {
    asm("mov.b64 {%0, %1}, %2;" : "=f"(lo), "=f"(hi) : "l"(v));
}
__device__ __forceinline__ u64 ffma2(u64 a, u64 b, u64 c) {
    u64 d; asm("fma.rn.f32x2 %0, %1, %2, %3;" : "=l"(d) : "l"(a), "l"(b), "l"(c));
    return d;
}

// ---------------------------------------------------------------------------
// Main: block = (dir, batch, query-tile of 256). Prep fused into staging.
// smem per candidate j: scA[j]=(-2x,-2x,-2y,-2y)  scB[j]=(-2z,-2z,|c|^2,|c|^2)
// ---------------------------------------------------------------------------
__global__ void __launch_bounds__(MAIN_THREADS)
chamfer_main_kernel(const float* __restrict__ p1, const float* __restrict__ p2) {
    __shared__ float4 scA[CTILE];
    __shared__ float4 scB[CTILE];
    __shared__ float  wsum[MAIN_THREADS / 32];

    int bx  = blockIdx.x;
    int dir = bx & 1;
    int b   = (bx >> 1) & 7;
    int qt  = bx >> 4;                       // 0..15

    const float* __restrict__ qsrc = ((dir == 0) ? p1 : p2) + b * NPTS * 3;
    const float* __restrict__ csrc = ((dir == 0) ? p2 : p1) + b * NPTS * 3;

    int t = threadIdx.x;
    int q0i = qt * QTILE + t;
    int q1i = q0i + MAIN_THREADS;

    float q0x = qsrc[3 * q0i + 0], q0y = qsrc[3 * q0i + 1], q0z = qsrc[3 * q0i + 2];
    float q1x = qsrc[3 * q1i + 0], q1y = qsrc[3 * q1i + 1], q1z = qsrc[3 * q1i + 2];
    float qn0 = fmaf(q0x, q0x, fmaf(q0y, q0y, q0z * q0z));
    float qn1 = fmaf(q1x, q1x, fmaf(q1y, q1y, q1z * q1z));

    u64 qx = pack2(q0x, q1x);
    u64 qy = pack2(q0y, q1y);
    u64 qz = pack2(q0z, q1z);

    // Split min accumulators break the FMNMX loop-carry chain.
    float m0a = CUDART_INF_F, m0b = CUDART_INF_F;
    float m1a = CUDART_INF_F, m1b = CUDART_INF_F;

    for (int ct = 0; ct < NPTS; ct += CTILE) {
        // Stage 4 candidates per thread: 12 consecutive floats = 3 x LDG.128.
        // (ct*12 bytes and t*48 bytes are both 16B-aligned.)
        const float4* src4 = (const float4*)(csrc + 3 * ct) + 3 * t;
        float4 v0 = src4[0];
        float4 v1 = src4[1];
        float4 v2 = src4[2];

        float cx[4] = { v0.x, v0.w, v1.z, v2.y };
        float cy[4] = { v0.y, v1.x, v1.w, v2.z };
        float cz[4] = { v0.z, v1.y, v2.x, v2.w };
        #pragma unroll
        for (int k = 0; k < 4; ++k) {
            float x = cx[k], y = cy[k], z = cz[k];
            float n = fmaf(x, x, fmaf(y, y, z * z));
            int idx = 4 * t + k;
            scA[idx] = make_float4(-2.0f * x, -2.0f * x, -2.0f * y, -2.0f * y);
            scB[idx] = make_float4(-2.0f * z, -2.0f * z, n, n);
        }
        __syncthreads();

        const ulonglong2* A = (const ulonglong2*)scA;
        const ulonglong2* B = (const ulonglong2*)scB;

        #pragma unroll 8
        for (int j = 0; j < CTILE; ++j) {
            ulonglong2 a = A[j];                 // a.x={-2x,-2x} a.y={-2y,-2y}
            ulonglong2 c = B[j];                 // c.x={-2z,-2z} c.y={n,n}
            u64 d = ffma2(a.x, qx, ffma2(a.y, qy, ffma2(c.x, qz, c.y)));
            float d0, d1;
            unpack2(d, d0, d1);
            if (j & 1) { m0b = fminf(m0b, d0); m1b = fminf(m1b, d1); }
            else       { m0a = fminf(m0a, d0); m1a = fminf(m1a, d1); }
        }
        __syncthreads();
    }

    float m0 = fminf(m0a, m0b);
    float m1 = fminf(m1a, m1b);
    float s = (qn0 + m0) + (qn1 + m1);

    // Deterministic block reduction.
    #pragma unroll
    for (int off = 16; off > 0; off >>= 1)
        s += __shfl_down_sync(0xffffffffu, s, off);
    if ((t & 31) == 0) wsum[t >> 5] = s;
    __syncthreads();
    if (t == 0) {
        float p = 0.0f;
        #pragma unroll
        for (int w = 0; w < MAIN_THREADS / 32; ++w) p += wsum[w];
        g_partial[bx] = p;
    }
}

// ---------------------------------------------------------------------------
// Final: deterministic sum of 256 partials -> loss scalar.
// ---------------------------------------------------------------------------
__global__ void chamfer_final_kernel(float* __restrict__ out) {
    __shared__ float wsum[MAIN_BLOCKS / 32];
    int t = threadIdx.x;
    float s = g_partial[t];
    #pragma unroll
    for (int off = 16; off > 0; off >>= 1)
        s += __shfl_down_sync(0xffffffffu, s, off);
    if ((t & 31) == 0) wsum[t >> 5] = s;
    __syncthreads();
    if (t == 0) {
        float tot = 0.0f;
        #pragma unroll
        for (int w = 0; w < MAIN_BLOCKS / 32; ++w) tot += wsum[w];
        out[0] = tot * (1.0f / (float)(BATCH * NPTS));
    }
}

extern "C" void kernel_launch(void* const* d_in, const int* in_sizes, int n_in,
                              void* d_out, int out_size) {
    const float* p1 = (const float*)d_in[0];
    const float* p2 = (const float*)d_in[1];
    float* out = (float*)d_out;

    chamfer_main_kernel<<<MAIN_BLOCKS, MAIN_THREADS>>>(p1, p2);
    chamfer_final_kernel<<<1, MAIN_BLOCKS>>>(out);
}

// round 4
// speedup vs baseline: 1.5606x; 1.5606x over previous
#include <cuda_runtime.h>
#include <math_constants.h>

// ChamferDistanceLoss, B=8, N=4096, D=3 — FUSED both directions.
// Each (p1_i, p2_j) pair computed ONCE: d = rn_i + cn_j - 2 p1_i.p2_j.
// Row-mins (p1 side) accumulate in registers; col-mins (p2 side) use an
// XOR-rotation: lane l at step s handles column (l^s), value shuffled back
// to owner lane via __shfl_xor(.., s). 1 SHFL + 1 FMNMX per 64 pairs.

#define NPTS 4096
#define BATCH 8
#define RPB 128                     // rows per block
#define RT (NPTS / RPB)             // 32 row tiles
#define MAIN_BLOCKS (BATCH * RT)    // 256
#define THREADS 128
#define NWARPS 4
#define CSTAGE 2048                 // columns staged in smem per pass
#define NPASS (NPTS / CSTAGE)       // 2
#define WCOLS (CSTAGE / NWARPS)     // 512 columns per warp per pass
#define K2_THREADS 256
#define K2_BLOCKS (BATCH * NPTS / K2_THREADS)   // 128

__device__ float g_colpart[MAIN_BLOCKS * NPTS]; // 4 MB: per-(block) col-min partials
__device__ float g_rowsum[MAIN_BLOCKS];
__device__ float g_colsum[K2_BLOCKS];

// ---------------------------------------------------------------------------
// Main: block = (batch, 128-row tile). All 4096 columns streamed in 2 passes.
// Warp w owns columns [w*512, (w+1)*512) of the staged 2048.
// ---------------------------------------------------------------------------
__global__ void __launch_bounds__(THREADS, 2)
chamfer_main(const float* __restrict__ p1, const float* __restrict__ p2) {
    __shared__ float4 sc[CSTAGE];            // (-2x,-2y,-2z,|c|^2)  32 KB
    __shared__ float  s_colmin[CSTAGE];      // 8 KB
    __shared__ float  s_rowmin[NWARPS * RPB];// 2 KB
    __shared__ float  s_red[THREADS / 32];

    int bx = blockIdx.x;
    int b  = bx >> 5;
    int rt = bx & 31;
    const float* __restrict__ rows = p1 + (b * NPTS + rt * RPB) * 3;
    const float* __restrict__ cols = p2 + b * NPTS * 3;

    int t = threadIdx.x;
    int w = t >> 5;
    int lane = t & 31;

    for (int i = t; i < NWARPS * RPB; i += THREADS) s_rowmin[i] = CUDART_INF_F;

    for (int pass = 0; pass < NPASS; ++pass) {
        __syncthreads();   // protect sc / s_colmin reuse from previous pass

        // Stage 2048 candidates: 4 per thread-group via 3x LDG.128 (16B-aligned:
        // pass stride = 2048*3*4B, group stride = 48B).
        #pragma unroll
        for (int g = 0; g < CSTAGE / (4 * THREADS); ++g) {
            int ci = t + g * THREADS;                       // group 0..511
            const float4* s4 = (const float4*)(cols + pass * CSTAGE * 3) + 3 * ci;
            float4 v0 = s4[0], v1 = s4[1], v2 = s4[2];
            float cx[4] = { v0.x, v0.w, v1.z, v2.y };
            float cy[4] = { v0.y, v1.x, v1.w, v2.z };
            float cz[4] = { v0.z, v1.y, v2.x, v2.w };
            #pragma unroll
            for (int k = 0; k < 4; ++k) {
                float x = cx[k], y = cy[k], z = cz[k];
                float n = fmaf(x, x, fmaf(y, y, z * z));
                sc[4 * ci + k] = make_float4(-2.0f * x, -2.0f * y, -2.0f * z, n);
            }
        }
        for (int i = t; i < CSTAGE; i += THREADS) s_colmin[i] = CUDART_INF_F;
        __syncthreads();

        #pragma unroll
        for (int chunk = 0; chunk < RPB / 64; ++chunk) {
            // This warp covers rows [chunk*64, chunk*64+64): 2 per lane.
            int r0i = chunk * 64 + lane;
            int r1i = r0i + 32;
            float rx0 = rows[3 * r0i + 0], ry0 = rows[3 * r0i + 1], rz0 = rows[3 * r0i + 2];
            float rx1 = rows[3 * r1i + 0], ry1 = rows[3 * r1i + 1], rz1 = rows[3 * r1i + 2];
            float rn0 = fmaf(rx0, rx0, fmaf(ry0, ry0, rz0 * rz0));
            float rn1 = fmaf(rx1, rx1, fmaf(ry1, ry1, rz1 * rz1));

            float rm0 = CUDART_INF_F, rm1 = CUDART_INF_F;

            for (int cc = 0; cc < WCOLS / 32; ++cc) {
                int base = w * WCOLS + cc * 32;
                const float4* cb = &sc[base];
                float cm = CUDART_INF_F;
                #pragma unroll 8
                for (int s = 0; s < 32; ++s) {
                    float4 c = cb[lane ^ s];              // conflict-free LDS.128
                    float b0 = c.w + rn0;
                    float b1 = c.w + rn1;
                    float w0 = fmaf(c.x, rx0, fmaf(c.y, ry0, fmaf(c.z, rz0, b0)));
                    float w1 = fmaf(c.x, rx1, fmaf(c.y, ry1, fmaf(c.z, rz1, b1)));
                    rm0 = fminf(rm0, w0);
                    rm1 = fminf(rm1, w1);
                    float cv = fminf(w0, w1);
                    float rc = __shfl_xor_sync(0xffffffffu, cv, s);
                    cm = fminf(cm, rc);
                }
                // lane exclusively owns column base+lane within this warp
                s_colmin[base + lane] = fminf(s_colmin[base + lane], cm);
            }
            // merge this chunk's row mins (slice exclusive to warp w)
            s_rowmin[w * RPB + r0i] = fminf(s_rowmin[w * RPB + r0i], rm0);
            s_rowmin[w * RPB + r1i] = fminf(s_rowmin[w * RPB + r1i], rm1);
        }

        __syncthreads();
        // Flush this pass's col-min partials (columns disjoint across passes).
        for (int i = t; i < CSTAGE; i += THREADS)
            g_colpart[bx * NPTS + pass * CSTAGE + i] = s_colmin[i];
    }

    __syncthreads();
    // Row side: thread t owns row t; min over the 4 warp partials (full d incl rn).
    float m = s_rowmin[t];
    #pragma unroll
    for (int ww = 1; ww < NWARPS; ++ww) m = fminf(m, s_rowmin[ww * RPB + t]);
    float s = m;
    #pragma unroll
    for (int off = 16; off > 0; off >>= 1)
        s += __shfl_down_sync(0xffffffffu, s, off);
    if (lane == 0) s_red[w] = s;
    __syncthreads();
    if (t == 0) {
        float p = 0.0f;
        #pragma unroll
        for (int ww = 0; ww < THREADS / 32; ++ww) p += s_red[ww];
        g_rowsum[bx] = p;
    }
}

// ---------------------------------------------------------------------------
// K2: col-min over the 32 row-tile partials, then block-sum.
// ---------------------------------------------------------------------------
__global__ void chamfer_colreduce() {
    __shared__ float wsum[K2_THREADS / 32];
    int idx = blockIdx.x * K2_THREADS + threadIdx.x;   // 0..32767
    int b = idx >> 12;
    int j = idx & (NPTS - 1);
    float m = CUDART_INF_F;
    #pragma unroll
    for (int rtile = 0; rtile < RT; ++rtile)
        m = fminf(m, g_colpart[((b << 5) + rtile) * NPTS + j]);
    float s = m;
    int t = threadIdx.x;
    #pragma unroll
    for (int off = 16; off > 0; off >>= 1)
        s += __shfl_down_sync(0xffffffffu, s, off);
    if ((t & 31) == 0) wsum[t >> 5] = s;
    __syncthreads();
    if (t == 0) {
        float p = 0.0f;
        #pragma unroll
        for (int ww = 0; ww < K2_THREADS / 32; ++ww) p += wsum[ww];
        g_colsum[blockIdx.x] = p;
    }
}

// ---------------------------------------------------------------------------
// K3: deterministic final sum -> loss.
// ---------------------------------------------------------------------------
__global__ void chamfer_final(float* __restrict__ out) {
    __shared__ float wsum[4];
    int t = threadIdx.x;   // 128 threads
    float s = g_rowsum[t] + g_rowsum[t + 128] + g_colsum[t];
    #pragma unroll
    for (int off = 16; off > 0; off >>= 1)
        s += __shfl_down_sync(0xffffffffu, s, off);
    if ((t & 31) == 0) wsum[t >> 5] = s;
    __syncthreads();
    if (t == 0) {
        float tot = 0.0f;
        #pragma unroll
        for (int ww = 0; ww < 4; ++ww) tot += wsum[ww];
        out[0] = tot * (1.0f / (float)(BATCH * NPTS));
    }
}

extern "C" void kernel_launch(void* const* d_in, const int* in_sizes, int n_in,
                              void* d_out, int out_size) {
    const float* p1 = (const float*)d_in[0];
    const float* p2 = (const float*)d_in[1];
    float* out = (float*)d_out;

    chamfer_main<<<MAIN_BLOCKS, THREADS>>>(p1, p2);
    chamfer_colreduce<<<K2_BLOCKS, K2_THREADS>>>();
    chamfer_final<<<1, THREADS>>>(out);
}

// round 7
// speedup vs baseline: 2.1779x; 1.3956x over previous
#include <cuda_runtime.h>
#include <math_constants.h>
#include <cstdint>

// ChamferDistanceLoss, B=8, N=4096, D=3 — fused both directions.
// d(i,j) = rn_i + cn_j - 2 p1_i.p2_j computed ONCE per pair.
// Block = (batch, 128-row tile, 1024-col tile): 1024 blocks for occupancy.
// Warp owns a 256-col slice and ALL 128 rows (4/lane). XOR rotation: lane l
// at step s evaluates column l^s of a 32-col group; one shfl_xor routes the
// column value to its owner lane; owner writes final col-min straight to gmem.

#define NPTS 4096
#define BATCH 8
#define RPB 128
#define CPB 1024
#define RT 32
#define CT 4
#define MAIN_BLOCKS (BATCH * RT * CT)       // 1024
#define THREADS 128
#define NWARPS 4
#define WCOLS (CPB / NWARPS)                // 256
#define RED_THREADS 256
#define RED_BLOCKS (BATCH * NPTS / RED_THREADS)  // 128

__device__ float g_rowpart[MAIN_BLOCKS * NWARPS * RPB];  // 2 MB
__device__ float g_colpart[MAIN_BLOCKS * CPB];           // 4 MB
__device__ float g_sum[RED_BLOCKS];

// ---------------------------------------------------------------------------
__global__ void __launch_bounds__(THREADS, 6)
chamfer_main(const float* __restrict__ p1, const float* __restrict__ p2) {
    __shared__ float4 sc[CPB];               // (-2x,-2y,-2z,|c|^2)  16 KB

    int bx = blockIdx.x;
    int b  = bx >> 7;                        // batch
    int rt = (bx >> 2) & 31;                 // row tile
    int ct = bx & 3;                         // col tile
    const float* __restrict__ rows = p1 + (b * NPTS + rt * RPB) * 3;
    const float* __restrict__ cols = p2 + (b * NPTS + ct * CPB) * 3;

    int t = threadIdx.x, w = t >> 5, lane = t & 31;

    // Stage 1024 candidates: 8 per thread via 2 groups of 3x LDG.128.
    #pragma unroll
    for (int g = 0; g < CPB / (4 * THREADS); ++g) {
        int ci = t + g * THREADS;
        const float4* s4 = (const float4*)cols + 3 * ci;
        float4 v0 = s4[0], v1 = s4[1], v2 = s4[2];
        float cx[4] = { v0.x, v0.w, v1.z, v2.y };
        float cy[4] = { v0.y, v1.x, v1.w, v2.z };
        float cz[4] = { v0.z, v1.y, v2.x, v2.w };
        #pragma unroll
        for (int k = 0; k < 4; ++k) {
            float x = cx[k], y = cy[k], z = cz[k];
            float n = fmaf(x, x, fmaf(y, y, z * z));
            sc[4 * ci + k] = make_float4(-2.0f * x, -2.0f * y, -2.0f * z, n);
        }
    }

    // 4 rows per lane (whole 128-row tile per warp).
    float rx[4], ry[4], rz[4], rn[4], rm[4];
    #pragma unroll
    for (int k = 0; k < 4; ++k) {
        int r = k * 32 + lane;
        rx[k] = rows[3 * r + 0];
        ry[k] = rows[3 * r + 1];
        rz[k] = rows[3 * r + 2];
        rn[k] = fmaf(rx[k], rx[k], fmaf(ry[k], ry[k], rz[k] * rz[k]));
        rm[k] = CUDART_INF_F;
    }
    __syncthreads();

    const char* sbase = (const char*)sc;
    #pragma unroll
    for (int cc = 0; cc < WCOLS / 32; ++cc) {            // 8 groups of 32 cols
        uint32_t off0 = (uint32_t)(w * WCOLS + cc * 32 + lane) * 16u;
        float cm = CUDART_INF_F;
        #pragma unroll 8
        for (int s = 0; s < 32; ++s) {
            float4 c = *(const float4*)(sbase + (off0 ^ ((uint32_t)s << 4)));
            float w0 = fmaf(c.x, rx[0], fmaf(c.y, ry[0], fmaf(c.z, rz[0], c.w + rn[0])));
            float w1 = fmaf(c.x, rx[1], fmaf(c.y, ry[1], fmaf(c.z, rz[1], c.w + rn[1])));
            float w2 = fmaf(c.x, rx[2], fmaf(c.y, ry[2], fmaf(c.z, rz[2], c.w + rn[2])));
            float w3 = fmaf(c.x, rx[3], fmaf(c.y, ry[3], fmaf(c.z, rz[3], c.w + rn[3])));
            rm[0] = fminf(rm[0], w0);
            rm[1] = fminf(rm[1], w1);
            rm[2] = fminf(rm[2], w2);
            rm[3] = fminf(rm[3], w3);
            float cv = fminf(fminf(w0, w1), fminf(w2, w3));
            cm = fminf(cm, __shfl_xor_sync(0xffffffffu, cv, s));
        }
        // This warp reduced column (base + lane) over all 128 rows: final partial.
        g_colpart[bx * CPB + w * WCOLS + cc * 32 + lane] = cm;
    }

    // Row partials: full-d min over this warp's 256 cols (rn already folded in).
    #pragma unroll
    for (int k = 0; k < 4; ++k)
        g_rowpart[(bx * NWARPS + w) * RPB + k * 32 + lane] = rm[k];
}

// ---------------------------------------------------------------------------
// Reduce: thread i owns global row i and global col i (both 0..32767):
// row-min over 16 partials (4 ct x 4 warps), col-min over 32 partials (rt).
// ---------------------------------------------------------------------------
__global__ void chamfer_reduce() {
    __shared__ float wsum[RED_THREADS / 32];
    int i = blockIdx.x * RED_THREADS + threadIdx.x;      // 0..32767
    int b = i >> 12;
    int r = i & (NPTS - 1);

    // Row side: (b, rt=r>>7, rr=r&127), min over ct, w.
    int rt = r >> 7, rr = r & 127;
    float rmin = CUDART_INF_F;
    #pragma unroll
    for (int c = 0; c < CT; ++c)
        #pragma unroll
        for (int ww = 0; ww < NWARPS; ++ww)
            rmin = fminf(rmin,
                g_rowpart[(((b * RT + rt) * CT + c) * NWARPS + ww) * RPB + rr]);

    // Col side: (b, ctile=r>>10, cc=r&1023), min over rt.
    int ctile = r >> 10, ccx = r & (CPB - 1);
    float cmin = CUDART_INF_F;
    #pragma unroll
    for (int rr2 = 0; rr2 < RT; ++rr2)
        cmin = fminf(cmin,
            g_colpart[((b * RT + rr2) * CT + ctile) * CPB + ccx]);

    float s = rmin + cmin;
    int t = threadIdx.x;
    #pragma unroll
    for (int off = 16; off > 0; off >>= 1)
        s += __shfl_down_sync(0xffffffffu, s, off);
    if ((t & 31) == 0) wsum[t >> 5] = s;
    __syncthreads();
    if (t == 0) {
        float p = 0.0f;
        #pragma unroll
        for (int ww = 0; ww < RED_THREADS / 32; ++ww) p += wsum[ww];
        g_sum[blockIdx.x] = p;
    }
}

// ---------------------------------------------------------------------------
__global__ void chamfer_final(float* __restrict__ out) {
    __shared__ float wsum[4];
    int t = threadIdx.x;                                  // 128
    float s = g_sum[t];
    #pragma unroll
    for (int off = 16; off > 0; off >>= 1)
        s += __shfl_down_sync(0xffffffffu, s, off);
    if ((t & 31) == 0) wsum[t >> 5] = s;
    __syncthreads();
    if (t == 0) {
        float tot = 0.0f;
        #pragma unroll
        for (int ww = 0; ww < 4; ++ww) tot += wsum[ww];
        out[0] = tot * (1.0f / (float)(BATCH * NPTS));
    }
}

extern "C" void kernel_launch(void* const* d_in, const int* in_sizes, int n_in,
                              void* d_out, int out_size) {
    const float* p1 = (const float*)d_in[0];
    const float* p2 = (const float*)d_in[1];
    float* out = (float*)d_out;

    chamfer_main<<<MAIN_BLOCKS, THREADS>>>(p1, p2);
    chamfer_reduce<<<RED_BLOCKS, RED_THREADS>>>();
    chamfer_final<<<1, THREADS>>>(out);
}